// round 2
// baseline (speedup 1.0000x reference)
#include <cuda_runtime.h>
#include <math.h>

#define B_  4096
#define D_  5000
#define H_  512
#define H2_ 1024
#define Z_  64

// ---------------- scratch (static device globals; no allocs) ----------------
__device__ float g_h  [B_ * H_ ];
__device__ float g_w  [B_ * D_ ];
__device__ float g_xm [B_ * D_ ];
__device__ float g_h1a[B_ * H2_];
__device__ float g_h1b[B_ * H_ ];
__device__ float g_h1c[B_ * H_ ];
__device__ float g_z  [B_ * Z_ ];
__device__ float g_scale[H_];
__device__ float g_shift[H_];

// ---------------- generic fp32 tiled GEMM with fused epilogues ----------------
// C[M,N] = epi( Atrans(A)[M,K] @ B[K,N] + bias[N] )
// AMODE: 0 = raw A; 1 = relu(A*ascale[k] + ashift[k])  (fused BatchNorm+ReLU)
// EPI:   0 = bias; 1 = bias+leaky(0.01); 2 = bias+sigmoid; 3 = bias + log(-log(u))
// Requirements: M % 128 == 0, K % 8 == 0 (all shapes here satisfy both).
template<int AMODE, int EPI>
__global__ void __launch_bounds__(256) sgemm_k(
    const float* __restrict__ A, const float* __restrict__ Bm,
    const float* __restrict__ bias, float* __restrict__ C,
    int M, int N, int K,
    const float* __restrict__ asc, const float* __restrict__ ash,
    const float* __restrict__ U)
{
    constexpr int BM = 128, BN = 128, BK = 8, TM = 8, TN = 8;
    __shared__ float As[BK][BM];
    __shared__ float Bs[BK][BN];

    const int tid = threadIdx.x;
    const int tx  = tid & 15;        // 0..15 (column group)
    const int ty  = tid >> 4;        // 0..15 (row group)
    const int bm  = blockIdx.y * BM;
    const int bn  = blockIdx.x * BN;

    // A tile load mapping: 128x8 = 1024 floats, float4 per thread
    const int aIdx = tid * 4;
    const int am   = aIdx >> 3;      // /BK
    const int ak   = aIdx & 7;
    // B tile load mapping: 8x128 = 1024 floats, 4 scalars per thread (N-guarded)
    const int bIdx = tid * 4;
    const int bk   = bIdx >> 7;      // /BN
    const int bn4  = bIdx & 127;

    float acc[TM][TN];
#pragma unroll
    for (int i = 0; i < TM; i++)
#pragma unroll
        for (int j = 0; j < TN; j++) acc[i][j] = 0.f;

    const float* Aptr = A + (size_t)(bm + am) * K;

    for (int k0 = 0; k0 < K; k0 += BK) {
        float4 av = *(const float4*)(Aptr + k0 + ak);
        if (AMODE == 1) {
            int kk = k0 + ak;
            av.x = fmaxf(fmaf(av.x, asc[kk + 0], ash[kk + 0]), 0.f);
            av.y = fmaxf(fmaf(av.y, asc[kk + 1], ash[kk + 1]), 0.f);
            av.z = fmaxf(fmaf(av.z, asc[kk + 2], ash[kk + 2]), 0.f);
            av.w = fmaxf(fmaf(av.w, asc[kk + 3], ash[kk + 3]), 0.f);
        }
        As[ak + 0][am] = av.x;
        As[ak + 1][am] = av.y;
        As[ak + 2][am] = av.z;
        As[ak + 3][am] = av.w;

        {
            const float* Bp = Bm + (size_t)(k0 + bk) * N + bn + bn4;
            int nrem = N - (bn + bn4);
            Bs[bk][bn4 + 0] = (0 < nrem) ? Bp[0] : 0.f;
            Bs[bk][bn4 + 1] = (1 < nrem) ? Bp[1] : 0.f;
            Bs[bk][bn4 + 2] = (2 < nrem) ? Bp[2] : 0.f;
            Bs[bk][bn4 + 3] = (3 < nrem) ? Bp[3] : 0.f;
        }
        __syncthreads();

#pragma unroll
        for (int kk = 0; kk < BK; kk++) {
            float ar[TM], br[TN];
#pragma unroll
            for (int i = 0; i < TM; i++) ar[i] = As[kk][ty * TM + i];
#pragma unroll
            for (int j = 0; j < TN; j++) br[j] = Bs[kk][tx * TN + j];
#pragma unroll
            for (int i = 0; i < TM; i++)
#pragma unroll
                for (int j = 0; j < TN; j++)
                    acc[i][j] = fmaf(ar[i], br[j], acc[i][j]);
        }
        __syncthreads();
    }

#pragma unroll
    for (int i = 0; i < TM; i++) {
        int m = bm + ty * TM + i;
#pragma unroll
        for (int j = 0; j < TN; j++) {
            int n = bn + tx * TN + j;
            if (n < N) {
                float v = acc[i][j] + bias[n];
                if (EPI == 1) {
                    v = (v > 0.f) ? v : 0.01f * v;
                } else if (EPI == 2) {
                    v = 1.0f / (1.0f + expf(-v));
                } else if (EPI == 3) {
                    float u = U[(size_t)m * N + n];
                    u = (1.0f - 1e-30f) * u + 1e-30f;
                    v += logf(-logf(u));
                }
                C[(size_t)m * N + n] = v;
            }
        }
    }
}

// ---------------- BatchNorm column stats: scale/shift precompute ----------------
__global__ void bnstats_k(const float* __restrict__ Hm,
                          const float* __restrict__ gamma,
                          const float* __restrict__ beta,
                          float* __restrict__ sc, float* __restrict__ sh)
{
    int c = blockIdx.x;   // 0..H_-1
    float s = 0.f, q = 0.f;
    for (int r = threadIdx.x; r < B_; r += blockDim.x) {
        float v = Hm[(size_t)r * H_ + c];
        s += v;
        q += v * v;
    }
#pragma unroll
    for (int o = 16; o > 0; o >>= 1) {
        s += __shfl_down_sync(0xffffffffu, s, o);
        q += __shfl_down_sync(0xffffffffu, q, o);
    }
    __shared__ float rs[8], rq[8];
    int w = threadIdx.x >> 5, l = threadIdx.x & 31;
    if (l == 0) { rs[w] = s; rq[w] = q; }
    __syncthreads();
    if (threadIdx.x == 0) {
        float S = 0.f, Q = 0.f;
        for (int i = 0; i < 8; i++) { S += rs[i]; Q += rq[i]; }
        float mean  = S / (float)B_;
        float var   = Q / (float)B_ - mean * mean;   // biased var (matches jnp.var)
        float scale = gamma[c] * rsqrtf(var + 1e-5f);
        sc[c] = scale;
        sh[c] = beta[c] - mean * scale;
    }
}

// ---------------- register-resident continuous top-k (+ fused xm = x*subset) --
// One block per row. 512 threads x 10 elems = 5120 >= 5000. 50 iterations of
// softmax(w/T) recurrence entirely in registers; only 2 block reductions/iter.
// Elements with (w-max)/T < -20 contribute <1e-8 to the softmax and are skipped.
__global__ void __launch_bounds__(512) topk_k(const float* __restrict__ W,
                                              const float* __restrict__ X,
                                              float* __restrict__ XM)
{
    constexpr int NT = 512, EPT = 10;
    int row = blockIdx.x;
    const float* wr = W + (size_t)row * D_;
    int t = threadIdx.x;

    float wv[EPT], sv[EPT];
#pragma unroll
    for (int i = 0; i < EPT; i++) {
        int idx = t + i * NT;
        wv[i] = (idx < D_) ? wr[idx] : -3.0e38f;
        sv[i] = 0.f;
    }

    __shared__ float red[16];
    __shared__ float bc_max, bc_sum;
    int w = t >> 5, l = t & 31;

    for (int it = 0; it < 50; it++) {
        // ---- block max ----
        float m = wv[0];
#pragma unroll
        for (int i = 1; i < EPT; i++) m = fmaxf(m, wv[i]);
#pragma unroll
        for (int o = 16; o > 0; o >>= 1) m = fmaxf(m, __shfl_xor_sync(0xffffffffu, m, o));
        if (l == 0) red[w] = m;
        __syncthreads();
        if (t == 0) {
            float mm = red[0];
            for (int i = 1; i < 16; i++) mm = fmaxf(mm, red[i]);
            bc_max = mm;
        }
        __syncthreads();
        float mx = bc_max;

        // ---- block sum of exp((w-mx)/T), thresholded ----
        float s = 0.f;
        float ev[EPT];
#pragma unroll
        for (int i = 0; i < EPT; i++) {
            float a = (wv[i] - mx) * 10.0f;   // 1/T = 10
            float e = (a > -20.f) ? __expf(a) : 0.f;
            ev[i] = e;
            s += e;
        }
#pragma unroll
        for (int o = 16; o > 0; o >>= 1) s += __shfl_xor_sync(0xffffffffu, s, o);
        if (l == 0) red[w] = s;
        __syncthreads();
        if (t == 0) {
            float ss = 0.f;
            for (int i = 0; i < 16; i++) ss += red[i];
            bc_sum = ss;
        }
        __syncthreads();
        float inv = 1.0f / bc_sum;

        // ---- accumulate khot, apply mask update ----
#pragma unroll
        for (int i = 0; i < EPT; i++) {
            float oh = ev[i] * inv;
            sv[i] += oh;
            if (oh > 0.f) wv[i] += __logf(fmaxf(1.0f - oh, 1e-30f));
        }
    }

    const float* xr = X + (size_t)row * D_;
    float*       xo = XM + (size_t)row * D_;
#pragma unroll
    for (int i = 0; i < EPT; i++) {
        int idx = t + i * NT;
        if (idx < D_) xo[idx] = xr[idx] * sv[i];
    }
}

// ---------------- reparameterize ----------------
__global__ void z_k(const float* __restrict__ mu, const float* __restrict__ lv,
                    const float* __restrict__ eps, float* __restrict__ z, int n)
{
    int i = blockIdx.x * blockDim.x + threadIdx.x;
    if (i < n) z[i] = mu[i] + eps[i] * expf(0.5f * lv[i]);
}

// ---------------- launch ----------------
static inline dim3 ggrid(int M, int N) { return dim3((N + 127) / 128, M / 128); }

extern "C" void kernel_launch(void* const* d_in, const int* in_sizes, int n_in,
                              void* d_out, int out_size)
{
    const float* x      = (const float*)d_in[0];
    const float* noise  = (const float*)d_in[1];
    const float* epsv   = (const float*)d_in[2];
    const float* wc_w1  = (const float*)d_in[3];
    const float* wc_b1  = (const float*)d_in[4];
    const float* bn_g   = (const float*)d_in[5];
    const float* bn_b   = (const float*)d_in[6];
    const float* wc_w2  = (const float*)d_in[7];
    const float* wc_b2  = (const float*)d_in[8];
    const float* enc_w1 = (const float*)d_in[9];
    const float* enc_b1 = (const float*)d_in[10];
    const float* enc_w2 = (const float*)d_in[11];
    const float* enc_b2 = (const float*)d_in[12];
    const float* enc_w3 = (const float*)d_in[13];
    const float* enc_b3 = (const float*)d_in[14];
    const float* enc_w4 = (const float*)d_in[15];
    const float* enc_b4 = (const float*)d_in[16];
    const float* mean_w = (const float*)d_in[17];
    const float* mean_b = (const float*)d_in[18];
    const float* lv_w   = (const float*)d_in[19];
    const float* lv_b   = (const float*)d_in[20];
    const float* dec_w1 = (const float*)d_in[21];
    const float* dec_b1 = (const float*)d_in[22];
    const float* dec_w2 = (const float*)d_in[23];
    const float* dec_b2 = (const float*)d_in[24];

    float* out      = (float*)d_out;
    float* out_mu_x = out;                                   // [B, D]
    float* out_mu   = out + (size_t)B_ * D_;                 // [B, Z]
    float* out_lv   = out + (size_t)B_ * D_ + (size_t)B_ * Z_; // [B, Z]

    float *ph, *pw, *pxm, *ph1a, *ph1b, *ph1c, *pz, *psc, *psh;
    cudaGetSymbolAddress((void**)&ph,   g_h);
    cudaGetSymbolAddress((void**)&pw,   g_w);
    cudaGetSymbolAddress((void**)&pxm,  g_xm);
    cudaGetSymbolAddress((void**)&ph1a, g_h1a);
    cudaGetSymbolAddress((void**)&ph1b, g_h1b);
    cudaGetSymbolAddress((void**)&ph1c, g_h1c);
    cudaGetSymbolAddress((void**)&pz,   g_z);
    cudaGetSymbolAddress((void**)&psc,  g_scale);
    cudaGetSymbolAddress((void**)&psh,  g_shift);

    dim3 blk(256);

    // weight_creator
    sgemm_k<0, 0><<<ggrid(B_, H_), blk>>>(x, wc_w1, wc_b1, ph, B_, H_, D_,
                                          nullptr, nullptr, nullptr);
    bnstats_k<<<H_, 256>>>(ph, bn_g, bn_b, psc, psh);
    sgemm_k<1, 3><<<ggrid(B_, D_), blk>>>(ph, wc_w2, wc_b2, pw, B_, D_, H_,
                                          psc, psh, noise);

    // differentiable top-k + feature masking
    topk_k<<<B_, 512>>>(pw, x, pxm);

    // encoder
    sgemm_k<0, 1><<<ggrid(B_, H2_), blk>>>(pxm,  enc_w1, enc_b1, ph1a, B_, H2_, D_,  0, 0, 0);
    sgemm_k<0, 1><<<ggrid(B_, H_ ), blk>>>(ph1a, enc_w2, enc_b2, ph1b, B_, H_,  H2_, 0, 0, 0);
    sgemm_k<0, 1><<<ggrid(B_, H_ ), blk>>>(ph1b, enc_w3, enc_b3, ph1c, B_, H_,  H_,  0, 0, 0);
    sgemm_k<0, 1><<<ggrid(B_, H_ ), blk>>>(ph1c, enc_w4, enc_b4, ph1b, B_, H_,  H_,  0, 0, 0);
    sgemm_k<0, 0><<<ggrid(B_, Z_ ), blk>>>(ph1b, mean_w, mean_b, out_mu, B_, Z_, H_, 0, 0, 0);
    sgemm_k<0, 0><<<ggrid(B_, Z_ ), blk>>>(ph1b, lv_w,   lv_b,   out_lv, B_, Z_, H_, 0, 0, 0);

    // reparameterize
    z_k<<<(B_ * Z_ + 255) / 256, 256>>>(out_mu, out_lv, epsv, pz, B_ * Z_);

    // decoder
    sgemm_k<0, 1><<<ggrid(B_, H2_), blk>>>(pz,   dec_w1, dec_b1, ph1a,     B_, H2_, Z_,  0, 0, 0);
    sgemm_k<0, 2><<<ggrid(B_, D_ ), blk>>>(ph1a, dec_w2, dec_b2, out_mu_x, B_, D_,  H2_, 0, 0, 0);
}